// round 4
// baseline (speedup 1.0000x reference)
#include <cuda_runtime.h>
#include <math.h>

// Problem constants
#define TT   128
#define BB   64
#define INS  128
#define HH   512
#define NN   2048
#define WW   64
#define OO   128
#define RRh  4
#define CTRL (INS + RRh*WW)      // 384
#define NH   (OO + (RRh+1)*WW)   // 448
#define EPSF 1e-8f

#define GRID 128                 // <= 148 SMs: all CTAs wave-1 resident
#define NTH  256

// Persistent device state (no allocations allowed)
__device__ float g_M[BB*NN*WW];            // 33.5 MB memory matrix
__device__ float g_h[BB*HH];
__device__ float g_c[BB*HH];
__device__ float g_usage[BB*NN];
__device__ float g_rw[2][BB*RRh*NN];       // read weights double buffer
__device__ float g_readvec[BB*RRh*WW];
__device__ float g_gates_part[4][BB*4*HH]; // split-K partials for gates GEMM
__device__ float g_heads[BB*NH];
__device__ float g_rv_part[BB*16*RRh*WW];  // per-tile read_vec partials
__device__ int   g_lu[BB];                 // least-used slot per batch
__device__ unsigned g_arrive;              // monotonic barrier counter (never reset)

__device__ __forceinline__ float sigm(float x){ return 1.f/(1.f+expf(-x)); }

// Grid-wide barrier: monotonic cumulative counter -> no reset race, replay-safe.
// All GRID CTAs are co-resident (grid <= SM count), so spinning is safe.
__device__ __forceinline__ void gsync(){
    __syncthreads();
    if (threadIdx.x == 0){
        __threadfence();
        unsigned old = atomicAdd(&g_arrive, 1u);
        unsigned target = (old/GRID + 1u)*GRID;
        while (*(volatile unsigned*)&g_arrive < target) { }
        __threadfence();
    }
    __syncthreads();
}

__global__ __launch_bounds__(NTH, 1) void mann_persistent(
    const float* __restrict__ x,    const float* __restrict__ Wih,
    const float* __restrict__ Whh,  const float* __restrict__ bih,
    const float* __restrict__ bhh,  const float* __restrict__ Wout,
    const float* __restrict__ bout, const float* __restrict__ Wkey,
    const float* __restrict__ bkey, const float* __restrict__ alpha_p,
    const float* __restrict__ gamma_p, float* __restrict__ out)
{
    __shared__ float SM[4608];     // 18KB, unioned across phases
    const int c    = blockIdx.x;
    const int tid  = threadIdx.x;
    const int lane = tid & 31, warp = tid >> 5;

    // ------------------- init (every launch: graph replays) -------------------
    for (int i = c*NTH + tid; i < BB*NN*WW;  i += GRID*NTH) g_M[i] = 1e-6f;
    for (int i = c*NTH + tid; i < BB*HH;     i += GRID*NTH){ g_h[i]=0.f; g_c[i]=0.f; }
    for (int i = c*NTH + tid; i < BB*NN;     i += GRID*NTH) g_usage[i]=0.f;
    for (int i = c*NTH + tid; i < BB*RRh*NN; i += GRID*NTH){ g_rw[0][i]=0.f; g_rw[1][i]=0.f; }
    for (int i = c*NTH + tid; i < BB*RRh*WW; i += GRID*NTH) g_readvec[i]=0.f;
    if (c == 0 && tid < BB) g_lu[tid] = 0;   // argmin of all-zero usage = 0
    const float sa  = sigm(alpha_p[0]);
    const float gam = gamma_p[0];
    gsync();

    for (int t = 0; t < TT; t++){
        const int cur = t & 1, prev = cur ^ 1;
        const float* xt = x + (size_t)t*BB*INS;

        // ============ Phase 1: gates GEMM C[64,2048], K=896, split-K 4 =========
        // CTA c -> n-tile (c&31)*64, k-split (c>>5). 128 CTAs = exact mapping.
        {
            float (*As)[33] = (float(*)[33])SM;
            float (*Bs)[33] = (float(*)[33])(SM + 64*33);
            const int n0 = (c & 31)*64;
            const int ks = c >> 5;
            const int tx = tid & 15, ty = tid >> 4;
            float acc[4][4] = {};
            for (int kt = 0; kt < 7; kt++){
                const int kb = ks*224 + kt*32;
                for (int e = tid; e < 2048; e += NTH){
                    int row = e >> 5, kk = e & 31, gk = kb + kk;
                    float a;
                    if (gk < INS)       a = xt[row*INS + gk];
                    else if (gk < CTRL) a = g_readvec[row*(RRh*WW) + gk - INS];
                    else                a = g_h[row*HH + gk - CTRL];
                    As[row][kk] = a;
                    int n = n0 + row;
                    Bs[row][kk] = (gk < CTRL) ? Wih[n*CTRL + gk]
                                              : Whh[n*HH + gk - CTRL];
                }
                __syncthreads();
                #pragma unroll
                for (int kk = 0; kk < 32; kk++){
                    float a[4], b[4];
                    #pragma unroll
                    for (int i = 0; i < 4; i++) a[i] = As[ty*4+i][kk];
                    #pragma unroll
                    for (int j = 0; j < 4; j++) b[j] = Bs[tx*4+j][kk];
                    #pragma unroll
                    for (int i = 0; i < 4; i++)
                        #pragma unroll
                        for (int j = 0; j < 4; j++)
                            acc[i][j] += a[i]*b[j];
                }
                __syncthreads();
            }
            float* outp = g_gates_part[ks];
            #pragma unroll
            for (int i = 0; i < 4; i++)
                #pragma unroll
                for (int j = 0; j < 4; j++)
                    outp[(ty*4+i)*(4*HH) + n0 + tx*4 + j] = acc[i][j];
        }
        gsync();

        // ============ Phase 2: LSTM pointwise (combine split-K + bias) =========
        {
            int idx = c*NTH + tid;               // 0..32767 exactly
            int b = idx >> 9, u = idx & 511;
            int base = b*4*HH;
            float gi = 0.f, gf = 0.f, gg = 0.f, go = 0.f;
            #pragma unroll
            for (int p = 0; p < 4; p++){
                gi += g_gates_part[p][base + u];
                gf += g_gates_part[p][base + 512 + u];
                gg += g_gates_part[p][base + 1024 + u];
                go += g_gates_part[p][base + 1536 + u];
            }
            gi += bih[u]      + bhh[u];
            gf += bih[512+u]  + bhh[512+u];
            gg += bih[1024+u] + bhh[1024+u];
            go += bih[1536+u] + bhh[1536+u];
            float cv = sigm(gf)*g_c[idx] + sigm(gi)*tanhf(gg);
            g_c[idx] = cv;
            g_h[idx] = sigm(go)*tanhf(cv);
        }
        gsync();

        // ============ Phase 3: heads GEMM C[64,448], K=512 (fused bias+out) ====
        // 112 CTAs, n-tile of 4, full K per CTA: no split-K partials needed.
        if (c < 112){
            float* hs = SM;                      // [64][65]
            float* ws = SM + 64*65;              // [4][65]
            const int n0 = c*4;
            const int b  = tid & 63, nn = tid >> 6;
            const int n  = n0 + nn;
            float acc = 0.f;
            for (int kt = 0; kt < 8; kt++){
                const int kb = kt*64;
                #pragma unroll
                for (int i2 = 0; i2 < 16; i2++){
                    int idx = tid + i2*NTH;
                    int row = idx >> 6, col = idx & 63;
                    hs[row*65 + col] = g_h[row*HH + kb + col];
                }
                {
                    int wn = tid >> 6, col = tid & 63;
                    int gn = n0 + wn;
                    ws[wn*65 + col] = (gn < OO) ? Wout[gn*HH + kb + col]
                                                : Wkey[(gn-OO)*HH + kb + col];
                }
                __syncthreads();
                #pragma unroll
                for (int k = 0; k < 64; k++)
                    acc += hs[b*65 + k] * ws[nn*65 + k];
                __syncthreads();
            }
            float v = acc + ((n < OO) ? bout[n] : bkey[n - OO]);
            g_heads[b*NH + n] = v;
            if (n < OO) out[(size_t)t*BB*OO + b*OO + n] = v;
        }
        gsync();

        // ============ Phase 4: similarity sim[b,r,n] (cosine, fused norms) =====
        // 1024 (b,tile) units over 128 CTAs, 8 each. Warp-per-memory-row.
        {
            float* Kn = SM;                      // 256 floats
            for (int j = 0; j < 8; j++){
                int unit = c + j*GRID;
                int b = unit >> 4, tile = unit & 15;
                __syncthreads();
                if (warp < RRh){
                    const float* kp = &g_heads[b*NH + OO + warp*WW];
                    float k0 = kp[lane], k1 = kp[lane+32];
                    float ss = k0*k0 + k1*k1;
                    #pragma unroll
                    for (int o = 16; o; o >>= 1) ss += __shfl_xor_sync(0xffffffffu, ss, o);
                    float inv = 1.f/(sqrtf(ss) + EPSF);
                    Kn[warp*WW + lane]      = k0*inv;
                    Kn[warp*WW + lane + 32] = k1*inv;
                }
                __syncthreads();
                float* simp = &g_rw[cur][(size_t)b*RRh*NN];
                for (int i = 0; i < 16; i++){
                    int n = tile*128 + warp*16 + i;
                    const float* Mp = &g_M[((size_t)b*NN + n)*WW];
                    float m0 = Mp[lane], m1 = Mp[lane+32];
                    float s  = m0*m0 + m1*m1;
                    float d0 = Kn[lane]*m0     + Kn[lane+32]*m1;
                    float d1 = Kn[64+lane]*m0  + Kn[64+lane+32]*m1;
                    float d2 = Kn[128+lane]*m0 + Kn[128+lane+32]*m1;
                    float d3 = Kn[192+lane]*m0 + Kn[192+lane+32]*m1;
                    #pragma unroll
                    for (int o = 16; o; o >>= 1){
                        s  += __shfl_xor_sync(0xffffffffu, s,  o);
                        d0 += __shfl_xor_sync(0xffffffffu, d0, o);
                        d1 += __shfl_xor_sync(0xffffffffu, d1, o);
                        d2 += __shfl_xor_sync(0xffffffffu, d2, o);
                        d3 += __shfl_xor_sync(0xffffffffu, d3, o);
                    }
                    if (lane == 0){
                        float inv = 1.f/(sqrtf(s) + EPSF);
                        simp[0*NN + n] = d0*inv;
                        simp[1*NN + n] = d1*inv;
                        simp[2*NN + n] = d2*inv;
                        simp[3*NN + n] = d3*inv;
                    }
                }
            }
        }
        gsync();

        // ============ Phase 5: softmax over N, rows 2c and 2c+1 ================
        {
            float* red = SM;                     // 256 floats
            for (int rr = 0; rr < 2; rr++){
                int row = c*2 + rr;              // 0..255 = b*4+r
                float* p = &g_rw[cur][(size_t)row*NN];
                __syncthreads();
                float v[8];
                #pragma unroll
                for (int jj = 0; jj < 8; jj++) v[jj] = p[tid + jj*256];
                float mx = v[0];
                #pragma unroll
                for (int jj = 1; jj < 8; jj++) mx = fmaxf(mx, v[jj]);
                red[tid] = mx; __syncthreads();
                for (int s = 128; s; s >>= 1){
                    if (tid < s) red[tid] = fmaxf(red[tid], red[tid+s]);
                    __syncthreads();
                }
                mx = red[0]; __syncthreads();
                float sum = 0.f;
                #pragma unroll
                for (int jj = 0; jj < 8; jj++){ v[jj] = expf(v[jj]-mx); sum += v[jj]; }
                red[tid] = sum; __syncthreads();
                for (int s = 128; s; s >>= 1){
                    if (tid < s) red[tid] += red[tid+s];
                    __syncthreads();
                }
                float inv = 1.f/red[0];
                #pragma unroll
                for (int jj = 0; jj < 8; jj++) p[tid + jj*256] = v[jj]*inv;
            }
        }
        gsync();

        // ============ Phase 6: update (read_vec partials / M rewrite / usage) ==
        // w_w uses PREVIOUS step read weights; read_vec uses CURRENT (softmaxed);
        // read_vec accumulates against OLD M (read before rewrite, per-row safe).
        {
            float* wkey_s = SM;                  // 64
            float* pr     = SM + 64;             // 8*256
            for (int j = 0; j < 8; j++){
                int unit = c + j*GRID;
                int b = unit >> 4, tile = unit & 15;
                const int lu = g_lu[b];
                __syncthreads();
                if (tid < WW) wkey_s[tid] = g_heads[b*NH + OO + RRh*WW + tid];
                __syncthreads();
                const float* rc = &g_rw[cur][(size_t)b*RRh*NN];
                const float* rp = &g_rw[prev][(size_t)b*RRh*NN];
                const float wk0 = wkey_s[lane], wk1 = wkey_s[lane+32];
                float a00=0,a01=0,a10=0,a11=0,a20=0,a21=0,a30=0,a31=0;
                for (int i = 0; i < 16; i++){
                    int n = tile*128 + warp*16 + i;
                    float r0 = rc[n], r1 = rc[NN+n], r2 = rc[2*NN+n], r3 = rc[3*NN+n];
                    float ps = rp[n] + rp[NN+n] + rp[2*NN+n] + rp[3*NN+n];
                    float isLu = (n == lu) ? 1.f : 0.f;
                    float w_w  = sa*ps + (1.f-sa)*isLu;
                    float keep = 1.f - isLu;
                    float* Mp = &g_M[((size_t)b*NN + n)*WW];
                    float m0 = Mp[lane], m1 = Mp[lane+32];
                    a00 += r0*m0; a01 += r0*m1;
                    a10 += r1*m0; a11 += r1*m1;
                    a20 += r2*m0; a21 += r2*m1;
                    a30 += r3*m0; a31 += r3*m1;
                    Mp[lane]    = m0*keep + w_w*wk0;
                    Mp[lane+32] = m1*keep + w_w*wk1;
                    if (lane == 0)
                        g_usage[b*NN+n] = gam*g_usage[b*NN+n] + (r0+r1+r2+r3) + w_w;
                }
                pr[warp*256 + 0*WW+lane] = a00; pr[warp*256 + 0*WW+lane+32] = a01;
                pr[warp*256 + 1*WW+lane] = a10; pr[warp*256 + 1*WW+lane+32] = a11;
                pr[warp*256 + 2*WW+lane] = a20; pr[warp*256 + 2*WW+lane+32] = a21;
                pr[warp*256 + 3*WW+lane] = a30; pr[warp*256 + 3*WW+lane+32] = a31;
                __syncthreads();
                float s = 0.f;
                #pragma unroll
                for (int w2 = 0; w2 < 8; w2++) s += pr[w2*256 + tid];
                g_rv_part[(b*16 + tile)*256 + tid] = s;
            }
        }
        gsync();

        // ============ Phase 7: reduce read_vec + argmin(usage) =================
        if (c < BB){
            const int b = c;
            float s = 0.f;
            #pragma unroll
            for (int tl = 0; tl < 16; tl++) s += g_rv_part[(b*16 + tl)*256 + tid];
            g_readvec[b*256 + tid] = s;

            float* sv = SM;                      // 256
            int*   si = (int*)(SM + 256);        // 256
            float bv = 3.4e38f; int bi = 0x7fffffff;
            #pragma unroll
            for (int jj = 0; jj < 8; jj++){
                int n = tid + jj*256;
                float v = g_usage[b*NN + n];
                if (v < bv || (v == bv && n < bi)){ bv = v; bi = n; }
            }
            sv[tid] = bv; si[tid] = bi; __syncthreads();
            for (int st = 128; st; st >>= 1){
                if (tid < st){
                    float v2 = sv[tid+st]; int i2 = si[tid+st];
                    if (v2 < sv[tid] || (v2 == sv[tid] && i2 < si[tid])){
                        sv[tid] = v2; si[tid] = i2;
                    }
                }
                __syncthreads();
            }
            if (tid == 0) g_lu[b] = si[0];
        }
        gsync();
    }
}

// ---------------------------------------------------------------------------
extern "C" void kernel_launch(void* const* d_in, const int* in_sizes, int n_in,
                              void* d_out, int out_size){
    const float* x     = (const float*)d_in[0];
    const float* Wih   = (const float*)d_in[1];
    const float* Whh   = (const float*)d_in[2];
    const float* bih   = (const float*)d_in[3];
    const float* bhh   = (const float*)d_in[4];
    const float* Wout  = (const float*)d_in[5];
    const float* bout  = (const float*)d_in[6];
    const float* Wkey  = (const float*)d_in[7];
    const float* bkey  = (const float*)d_in[8];
    const float* alpha = (const float*)d_in[9];
    const float* gma   = (const float*)d_in[10];
    float* out = (float*)d_out;

    mann_persistent<<<GRID, NTH>>>(x, Wih, Whh, bih, bhh, Wout, bout,
                                   Wkey, bkey, alpha, gma, out);
}

// round 6
// speedup vs baseline: 2.4759x; 2.4759x over previous
#include <cuda_runtime.h>
#include <math.h>

// Problem constants
#define TT   128
#define BB   64
#define INS  128
#define HH   512
#define NN   2048
#define WW   64
#define OO   128
#define RRh  4
#define CTRL (INS + RRh*WW)      // 384
#define NH   (OO + (RRh+1)*WW)   // 448
#define EPSF 1e-8f

#define GRID 256                 // 2 CTAs/SM co-resident (296 slots >= 256)
#define NTH  256
#define KSPL 8                   // gates GEMM split-K
#define DYN_FLOATS 18304         // 73216 B dynamic smem per CTA (x2 = 146KB/SM)

// Persistent device state (no allocations allowed)
__device__ float g_M[BB*NN*WW];            // 33.5 MB memory matrix
__device__ float g_h[BB*HH];
__device__ float g_c[BB*HH];
__device__ float g_usage[BB*NN];
__device__ float g_rw[2][BB*RRh*NN];       // read weights double buffer
__device__ float g_readvec[BB*RRh*WW];
__device__ float g_gates_part[KSPL][BB*4*HH];
__device__ float g_heads[BB*NH];
__device__ float g_rv_part[BB*8*256];      // per-(b,tile) read_vec partials
__device__ int   g_lu[BB];                 // least-used slot per batch
__device__ unsigned g_arrive;              // monotonic barrier counter

__device__ __forceinline__ float sigm(float x){ return 1.f/(1.f+expf(-x)); }

// Grid barrier: monotonic cumulative counter -> replay-safe, no reset race.
// All GRID CTAs are co-resident (launch_bounds guarantees 2 CTAs/SM), so
// spinning cannot deadlock.
__device__ __forceinline__ void gsync(){
    __syncthreads();
    if (threadIdx.x == 0){
        __threadfence();
        unsigned old = atomicAdd(&g_arrive, 1u);
        unsigned target = (old/GRID + 1u)*GRID;
        while (*(volatile unsigned*)&g_arrive < target) { }
        __threadfence();
    }
    __syncthreads();
}

__global__ __launch_bounds__(NTH, 2) void mann_persistent(
    const float* __restrict__ x,    const float* __restrict__ Wih,
    const float* __restrict__ Whh,  const float* __restrict__ bih,
    const float* __restrict__ bhh,  const float* __restrict__ Wout,
    const float* __restrict__ bout, const float* __restrict__ Wkey,
    const float* __restrict__ bkey, const float* __restrict__ alpha_p,
    const float* __restrict__ gamma_p, float* __restrict__ out)
{
    extern __shared__ float dyn[];
    const int c    = blockIdx.x;
    const int tid  = threadIdx.x;
    const int lane = tid & 31, warp = tid >> 5;

    // ------------------- init (graph replays re-run this) --------------------
    for (int i = c*NTH + tid; i < BB*NN*WW;  i += GRID*NTH) g_M[i] = 1e-6f;
    for (int i = c*NTH + tid; i < BB*HH;     i += GRID*NTH){ g_h[i]=0.f; g_c[i]=0.f; }
    for (int i = c*NTH + tid; i < BB*NN;     i += GRID*NTH) g_usage[i]=0.f;
    for (int i = c*NTH + tid; i < BB*RRh*NN; i += GRID*NTH){ g_rw[0][i]=0.f; g_rw[1][i]=0.f; }
    for (int i = c*NTH + tid; i < BB*RRh*WW; i += GRID*NTH) g_readvec[i]=0.f;
    if (c == 0 && tid < BB) g_lu[tid] = 0;   // argmin of all-zero usage = 0
    const float sa  = sigm(alpha_p[0]);
    const float gam = gamma_p[0];
    gsync();

    for (int t = 0; t < TT; t++){
        const int cur = t & 1, prev = cur ^ 1;
        const float* xt = x + (size_t)t*BB*INS;

        // ===== Phase 1: gates GEMM C[64,2048], K=896, split-K 8 ===============
        // CTA -> n-tile (c&31)*64, k-split (c>>5) covering 112 K (7 chunks x16)
        {
            float* As = dyn;            // [64][17]
            float* Bs = dyn + 64*17;    // [64][17]
            const int n0 = (c & 31)*64;
            const int ks = c >> 5;
            const int tx = tid & 15, ty = tid >> 4;
            float acc[4][4] = {};
            for (int kt = 0; kt < 7; kt++){
                const int kb = ks*112 + kt*16;
                #pragma unroll
                for (int j = 0; j < 4; j++){
                    int e = tid + j*256;          // 1024 elems
                    int row = e >> 4, kk = e & 15, gk = kb + kk;
                    float a;
                    if (gk < INS)       a = xt[row*INS + gk];
                    else if (gk < CTRL) a = g_readvec[row*(RRh*WW) + gk - INS];
                    else                a = g_h[row*HH + gk - CTRL];
                    As[row*17 + kk] = a;
                    int n = n0 + row;
                    Bs[row*17 + kk] = (gk < CTRL) ? Wih[n*CTRL + gk]
                                                  : Whh[n*HH + gk - CTRL];
                }
                __syncthreads();
                #pragma unroll
                for (int kk = 0; kk < 16; kk++){
                    float a[4], b[4];
                    #pragma unroll
                    for (int i = 0; i < 4; i++) a[i] = As[(ty*4+i)*17 + kk];
                    #pragma unroll
                    for (int j = 0; j < 4; j++) b[j] = Bs[(tx*4+j)*17 + kk];
                    #pragma unroll
                    for (int i = 0; i < 4; i++)
                        #pragma unroll
                        for (int j = 0; j < 4; j++)
                            acc[i][j] += a[i]*b[j];
                }
                __syncthreads();
            }
            float* outp = g_gates_part[ks];
            #pragma unroll
            for (int i = 0; i < 4; i++)
                #pragma unroll
                for (int j = 0; j < 4; j++)
                    outp[(ty*4+i)*(4*HH) + n0 + tx*4 + j] = acc[i][j];
        }
        gsync();

        // ===== Phase 2: LSTM pointwise (combine 8 partials + bias) ============
        {
            int gid = c*NTH + tid;
            if (gid < BB*HH){
                int b = gid >> 9, u = gid & 511;
                int base = b*4*HH;
                float gi = 0.f, gf = 0.f, gg = 0.f, go = 0.f;
                #pragma unroll
                for (int p = 0; p < KSPL; p++){
                    gi += g_gates_part[p][base + u];
                    gf += g_gates_part[p][base + 512 + u];
                    gg += g_gates_part[p][base + 1024 + u];
                    go += g_gates_part[p][base + 1536 + u];
                }
                gi += bih[u]      + bhh[u];
                gf += bih[512+u]  + bhh[512+u];
                gg += bih[1024+u] + bhh[1024+u];
                go += bih[1536+u] + bhh[1536+u];
                float cv = sigm(gf)*g_c[gid] + sigm(gi)*tanhf(gg);
                g_c[gid] = cv;
                g_h[gid] = sigm(go)*tanhf(cv);
            }
        }
        gsync();

        // ===== Phase 3: heads GEMM C[64,448], K=512, 2 cols/CTA, split-K 2 ====
        if (c < 224){
            float* hs  = dyn;                // [64][65]
            float* ws  = dyn + 64*65;        // [2][65]
            float* red = dyn + 64*65 + 130;  // [256]
            const int n0c = c*2;
            const int b  = tid & 63, q = tid >> 6;       // q: (col,khalf)
            const int col = n0c + (q >> 1), kh = q & 1;
            float acc = 0.f;
            for (int kt = 0; kt < 8; kt++){
                const int kb = kt*64;
                #pragma unroll
                for (int i2 = 0; i2 < 16; i2++){
                    int idx = tid + i2*NTH;
                    int row = idx >> 6, kc = idx & 63;
                    hs[row*65 + kc] = g_h[row*HH + kb + kc];
                }
                if (tid < 128){
                    int wn = tid >> 6, kc = tid & 63;
                    int gn = n0c + wn;
                    ws[wn*65 + kc] = (gn < OO) ? Wout[gn*HH + kb + kc]
                                               : Wkey[(gn-OO)*HH + kb + kc];
                }
                __syncthreads();
                if ((kt >> 2) == kh){
                    #pragma unroll
                    for (int k = 0; k < 64; k++)
                        acc += hs[b*65 + k] * ws[(q>>1)*65 + k];
                }
                __syncthreads();
            }
            red[tid] = acc;
            __syncthreads();
            if (kh == 0){
                float v = red[tid] + red[tid + 64];
                v += (col < OO) ? bout[col] : bkey[col - OO];
                g_heads[b*NH + col] = v;
                if (col < OO) out[(size_t)t*BB*OO + b*OO + col] = v;
            }
        }
        gsync();

        // ===== Phase 4: similarity (cosine) — staged M tile, no shuffles ======
        // 512 units = b(64) x tile(8 of 256 rows); 2 units per CTA
        {
            float* Ms  = dyn;            // [256][65]
            float* Kn4 = dyn + 256*65;   // [64][4] interleaved (r fastest)
            #pragma unroll 1
            for (int j = 0; j < 2; j++){
                const int unit = c + j*GRID;
                const int b = unit >> 3, tile = unit & 7;
                const int n0 = tile*256;
                // normalized keys (warps 0..3, one key each)
                if (warp < RRh){
                    const float* kp = &g_heads[b*NH + OO + warp*WW];
                    float k0 = kp[lane], k1 = kp[lane+32];
                    float ss = k0*k0 + k1*k1;
                    #pragma unroll
                    for (int o = 16; o; o >>= 1) ss += __shfl_xor_sync(0xffffffffu, ss, o);
                    float inv = 1.f/(sqrtf(ss) + EPSF);
                    Kn4[lane*4 + warp]      = k0*inv;
                    Kn4[(lane+32)*4 + warp] = k1*inv;
                }
                // stage M tile: 4096 float4 slots, coalesced
                const float4* Mg = (const float4*)&g_M[((size_t)b*NN + n0)*WW];
                #pragma unroll
                for (int i = 0; i < 16; i++){
                    int idx = tid + i*256;
                    int row = idx >> 4, wq = idx & 15;
                    float4 v = Mg[idx];
                    float* d = &Ms[row*65 + wq*4];
                    d[0] = v.x; d[1] = v.y; d[2] = v.z; d[3] = v.w;
                }
                __syncthreads();
                // per-thread row dot: n = tid
                float s = 0.f, d0 = 0.f, d1 = 0.f, d2 = 0.f, d3 = 0.f;
                const float* Mr = &Ms[tid*65];
                #pragma unroll 8
                for (int w = 0; w < 64; w++){
                    float m = Mr[w];
                    float4 k = *(const float4*)&Kn4[w*4];
                    s  += m*m;
                    d0 += k.x*m; d1 += k.y*m; d2 += k.z*m; d3 += k.w*m;
                }
                float inv = 1.f/(sqrtf(s) + EPSF);
                float* simp = &g_rw[cur][(size_t)b*RRh*NN + n0 + tid];
                simp[0]    = d0*inv;
                simp[NN]   = d1*inv;
                simp[2*NN] = d2*inv;
                simp[3*NN] = d3*inv;
                __syncthreads();
            }
        }
        gsync();

        // ===== Phase 5: softmax over N=2048, one row per CTA ==================
        {
            float* red = dyn;
            const int row = c;               // 0..255 = b*4 + r
            float* p = &g_rw[cur][(size_t)row*NN];
            float v[8];
            #pragma unroll
            for (int jj = 0; jj < 8; jj++) v[jj] = p[tid + jj*256];
            float mx = v[0];
            #pragma unroll
            for (int jj = 1; jj < 8; jj++) mx = fmaxf(mx, v[jj]);
            red[tid] = mx; __syncthreads();
            for (int s = 128; s; s >>= 1){
                if (tid < s) red[tid] = fmaxf(red[tid], red[tid+s]);
                __syncthreads();
            }
            mx = red[0]; __syncthreads();
            float sum = 0.f;
            #pragma unroll
            for (int jj = 0; jj < 8; jj++){ v[jj] = expf(v[jj]-mx); sum += v[jj]; }
            red[tid] = sum; __syncthreads();
            for (int s = 128; s; s >>= 1){
                if (tid < s) red[tid] += red[tid+s];
                __syncthreads();
            }
            float inv = 1.f/red[0];
            #pragma unroll
            for (int jj = 0; jj < 8; jj++) p[tid + jj*256] = v[jj]*inv;
        }
        gsync();

        // ===== Phase 6: update — staged tile: rv partials / M rewrite / usage =
        // w_w uses PREVIOUS step read weights; read_vec uses CURRENT weights
        // against OLD M (staged copy read before the rewrite).
        {
            float* Ms    = dyn;                  // [256][65]
            float* rcs   = dyn + 16640;          // [4][256]
            float* wwv   = dyn + 17664;          // [256]
            float* keepv = dyn + 17920;          // [256]
            float* wkv   = dyn + 18176;          // [64]
            #pragma unroll 1
            for (int j = 0; j < 2; j++){
                const int unit = c + j*GRID;
                const int b = unit >> 3, tile = unit & 7;
                const int n0 = tile*256;
                const int lu = g_lu[b];
                // stage M tile
                const float4* Mg = (const float4*)&g_M[((size_t)b*NN + n0)*WW];
                #pragma unroll
                for (int i = 0; i < 16; i++){
                    int idx = tid + i*256;
                    int row = idx >> 4, wq = idx & 15;
                    float4 v = Mg[idx];
                    float* d = &Ms[row*65 + wq*4];
                    d[0] = v.x; d[1] = v.y; d[2] = v.z; d[3] = v.w;
                }
                // stage rc, compute w_w/keep, update usage (n = tid)
                {
                    const float* rc = &g_rw[cur][(size_t)b*RRh*NN + n0];
                    const float* rp = &g_rw[prev][(size_t)b*RRh*NN + n0];
                    float r0 = rc[tid], r1 = rc[NN+tid], r2 = rc[2*NN+tid], r3 = rc[3*NN+tid];
                    rcs[tid] = r0; rcs[256+tid] = r1; rcs[512+tid] = r2; rcs[768+tid] = r3;
                    float ps = rp[tid] + rp[NN+tid] + rp[2*NN+tid] + rp[3*NN+tid];
                    float isLu = ((n0 + tid) == lu) ? 1.f : 0.f;
                    float ww = sa*ps + (1.f-sa)*isLu;
                    wwv[tid]   = ww;
                    keepv[tid] = 1.f - isLu;
                    int un = b*NN + n0 + tid;
                    g_usage[un] = gam*g_usage[un] + (r0+r1+r2+r3) + ww;
                    if (tid < WW) wkv[tid] = g_heads[b*NH + OO + RRh*WW + tid];
                }
                __syncthreads();
                // (a) rv partial: thread (r,w), serial over 256 rows (old M)
                {
                    const int r = tid >> 6, w = tid & 63;
                    const float* rcr = &rcs[r*256];
                    float acc = 0.f;
                    #pragma unroll 8
                    for (int n = 0; n < 256; n++)
                        acc += rcr[n] * Ms[n*65 + w];
                    g_rv_part[(b*8 + tile)*256 + tid] = acc;
                }
                // (b) M rewrite (smem reads only; no ordering hazard vs (a))
                {
                    float4* Mo = (float4*)&g_M[((size_t)b*NN + n0)*WW];
                    #pragma unroll
                    for (int i = 0; i < 16; i++){
                        int idx = tid + i*256;
                        int row = idx >> 4, wq = idx & 15;
                        const float* m = &Ms[row*65 + wq*4];
                        float kr = keepv[row], ww = wwv[row];
                        float4 o;
                        o.x = m[0]*kr + ww*wkv[wq*4+0];
                        o.y = m[1]*kr + ww*wkv[wq*4+1];
                        o.z = m[2]*kr + ww*wkv[wq*4+2];
                        o.w = m[3]*kr + ww*wkv[wq*4+3];
                        Mo[idx] = o;
                    }
                }
                __syncthreads();
            }
        }
        gsync();

        // ===== Phase 7: reduce read_vec + argmin(usage) =======================
        if (c < BB){
            const int b = c;
            float s = 0.f;
            #pragma unroll
            for (int tl = 0; tl < 8; tl++) s += g_rv_part[(b*8 + tl)*256 + tid];
            g_readvec[b*256 + tid] = s;

            float* sv = dyn;                 // [256]
            int*   si = (int*)(dyn + 256);   // [256]
            float bv = 3.4e38f; int bi = 0x7fffffff;
            #pragma unroll
            for (int jj = 0; jj < 8; jj++){
                int n = tid + jj*256;
                float v = g_usage[b*NN + n];
                if (v < bv || (v == bv && n < bi)){ bv = v; bi = n; }
            }
            sv[tid] = bv; si[tid] = bi; __syncthreads();
            for (int st = 128; st; st >>= 1){
                if (tid < st){
                    float v2 = sv[tid+st]; int i2 = si[tid+st];
                    if (v2 < sv[tid] || (v2 == sv[tid] && i2 < si[tid])){
                        sv[tid] = v2; si[tid] = i2;
                    }
                }
                __syncthreads();
            }
            if (tid == 0) g_lu[b] = si[0];
        }
        gsync();
    }
}

// ---------------------------------------------------------------------------
extern "C" void kernel_launch(void* const* d_in, const int* in_sizes, int n_in,
                              void* d_out, int out_size){
    const float* x     = (const float*)d_in[0];
    const float* Wih   = (const float*)d_in[1];
    const float* Whh   = (const float*)d_in[2];
    const float* bih   = (const float*)d_in[3];
    const float* bhh   = (const float*)d_in[4];
    const float* Wout  = (const float*)d_in[5];
    const float* bout  = (const float*)d_in[6];
    const float* Wkey  = (const float*)d_in[7];
    const float* bkey  = (const float*)d_in[8];
    const float* alpha = (const float*)d_in[9];
    const float* gma   = (const float*)d_in[10];
    float* out = (float*)d_out;

    cudaFuncSetAttribute(mann_persistent,
                         cudaFuncAttributeMaxDynamicSharedMemorySize,
                         DYN_FLOATS*4);
    mann_persistent<<<GRID, NTH, DYN_FLOATS*4>>>(x, Wih, Whh, bih, bhh,
                                                 Wout, bout, Wkey, bkey,
                                                 alpha, gma, out);
}